// round 2
// baseline (speedup 1.0000x reference)
#include <cuda_runtime.h>

#define T_LEVELS    21
#define IN_DIM      4096
#define OUT_DIM     32
#define PREFIX_BITS 18
#define SUFFIX_BITS 2          // PREFIX + SUFFIX = 20 path bits; bit 20 is j0
#define N_PRE       (4 + OUT_DIM)

// Scratch for precomputed dot products (allowed: __device__ global, no alloc).
__device__ float g_pre[N_PRE];

// ---------------------------------------------------------------------------
// Kernel 1: 36 dot products of x (4096) with rows of in_left/in_right/out_layer0
//   g_pre[0..1] = left0  (incl. bias)
//   g_pre[2..3] = right0 (incl. bias)
//   g_pre[4..35]= x@W0.T + out_bias   (the base accumulator A0)
// ---------------------------------------------------------------------------
__global__ void precompute_kernel(const float* __restrict__ x,
                                  const float* __restrict__ wl,
                                  const float* __restrict__ wr,
                                  const float* __restrict__ bl,
                                  const float* __restrict__ br,
                                  const float* __restrict__ w0,
                                  const float* __restrict__ ob)
{
    int r = blockIdx.x;            // 0..35
    const float* src;
    if (r < 2)       src = wl + r * IN_DIM;
    else if (r < 4)  src = wr + (r - 2) * IN_DIM;
    else             src = w0 + (r - 4) * IN_DIM;

    // float4 loads: 4096 / 4 = 1024 float4s, 256 threads -> 4 each
    const float4* x4 = reinterpret_cast<const float4*>(x);
    const float4* s4 = reinterpret_cast<const float4*>(src);
    float s = 0.0f;
    #pragma unroll
    for (int i = threadIdx.x; i < IN_DIM / 4; i += 256) {
        float4 a = x4[i], b = s4[i];
        s = fmaf(a.x, b.x, s);
        s = fmaf(a.y, b.y, s);
        s = fmaf(a.z, b.z, s);
        s = fmaf(a.w, b.w, s);
    }

    __shared__ float red[8];
    #pragma unroll
    for (int o = 16; o > 0; o >>= 1) s += __shfl_down_sync(0xffffffffu, s, o);
    if ((threadIdx.x & 31) == 0) red[threadIdx.x >> 5] = s;
    __syncthreads();
    if (threadIdx.x == 0) {
        float tot = 0.0f;
        for (int w = 0; w < 8; w++) tot += red[w];
        float add;
        if (r < 2)      add = bl[r];
        else if (r < 4) add = br[r - 2];
        else            add = ob[r - 4];
        g_pre[r] = tot + add;
    }
}

// ---------------------------------------------------------------------------
// Kernel 2: binary-tree expansion.
// Thread t owns path bits s1..s18 (= bits 0..17 of t); it enumerates the
// 2 suffix bits s19,s20 and both j0 leaves, writing 8 rows of 32 floats.
// Suffix contributions are folded directly into the store values — no second
// accumulator array (the round-1 register hog).
// Warp lanes differ in the low bits => each store step writes 32 consecutive
// 128B rows (4KB coalesced per warp).
// ---------------------------------------------------------------------------
__global__ void __launch_bounds__(128, 5)
tree_kernel(const float* __restrict__ tl,   // (21,2,2)
            const float* __restrict__ tr,   // (21,2,2)
            const float* __restrict__ tbl,  // (21,2)
            const float* __restrict__ tbr,  // (21,2)
            const float* __restrict__ wout, // (21,32,2)
            float* __restrict__ out)
{
    __shared__ float s_wout[T_LEVELS * 64];  // [k][c][j] -> float2 per channel
    __shared__ float s_tree[T_LEVELS * 12];  // [k][branch]{m00,m01,m10,m11,b0,b1}
    __shared__ float s_pre[N_PRE];

    for (int i = threadIdx.x; i < T_LEVELS * 64; i += blockDim.x)
        s_wout[i] = wout[i];
    for (int i = threadIdx.x; i < T_LEVELS * 12; i += blockDim.x) {
        int k = i / 12, rem = i % 12, b = rem / 6, e = rem % 6;
        const float* M = b ? tr  : tl;
        const float* B = b ? tbr : tbl;
        s_tree[i] = (e < 4) ? M[k * 4 + e] : B[k * 2 + (e - 4)];
    }
    for (int i = threadIdx.x; i < N_PRE; i += blockDim.x)
        s_pre[i] = g_pre[i];
    __syncthreads();

    const float2* s_wout2 = reinterpret_cast<const float2*>(s_wout);

    const unsigned t = blockIdx.x * blockDim.x + threadIdx.x; // 2^18 threads

    // A = base accumulator; (va, vb) = v_k(a=0), v_k(a=1)
    float A[OUT_DIM];
    #pragma unroll
    for (int c = 0; c < OUT_DIM; c++) A[c] = s_pre[4 + c];
    float vax = s_pre[0], vay = s_pre[2];   // v0(0) = (left0[0], right0[0])
    float vbx = s_pre[1], vby = s_pre[3];   // v0(1) = (left0[1], right0[1])

    // ---- prefix walk: levels k = 0..17, bit b = s_{k+1} = bit k of t ----
    #pragma unroll 1
    for (int k = 0; k < PREFIX_BITS; k++) {
        unsigned b = (t >> k) & 1u;
        const float2* W = s_wout2 + k * 32;
        float vsx = b ? vbx : vax;
        float vsy = b ? vby : vay;
        #pragma unroll
        for (int c = 0; c < OUT_DIM; c++) {
            float2 w = W[c];
            A[c] = fmaf(w.x, vsx, fmaf(w.y, vsy, A[c]));
        }
        const float* M = s_tree + k * 12 + b * 6;
        float m00 = M[0], m01 = M[1], m10 = M[2], m11 = M[3], c0 = M[4], c1 = M[5];
        float nax = fmaf(m00, vax, fmaf(m01, vay, c0));
        float nay = fmaf(m10, vax, fmaf(m11, vay, c1));
        float nbx = fmaf(m00, vbx, fmaf(m01, vby, c0));
        float nby = fmaf(m10, vbx, fmaf(m11, vby, c1));
        vax = nax; vay = nay; vbx = nbx; vby = nby;
    }
    // checkpoint: v at level 18 is (vax,vay,vbx,vby) -- kept live, never mutated below

    const float2* W18 = s_wout2 + 18 * 32;
    const float2* W19 = s_wout2 + 19 * 32;
    const float2* W20 = s_wout2 + 20 * 32;

    // ---- suffix enumeration: bits b1=s19, b2=s20, leaves j0 in {0,1} ----
    #pragma unroll
    for (unsigned u = 0; u < 4; ++u) {
        unsigned b1 = u & 1u, b2 = (u >> 1) & 1u;

        // level 18: select + advance v
        float vs18x = b1 ? vbx : vax;
        float vs18y = b1 ? vby : vay;
        const float* M = s_tree + 18 * 12 + b1 * 6;
        float m00 = M[0], m01 = M[1], m10 = M[2], m11 = M[3], c0 = M[4], c1 = M[5];
        float pax = fmaf(m00, vax, fmaf(m01, vay, c0));   // v19(a)
        float pay = fmaf(m10, vax, fmaf(m11, vay, c1));
        float pbx = fmaf(m00, vbx, fmaf(m01, vby, c0));   // v19(b)
        float pby = fmaf(m10, vbx, fmaf(m11, vby, c1));

        // level 19: select + advance v
        float vs19x = b2 ? pbx : pax;
        float vs19y = b2 ? pby : pay;
        M = s_tree + 19 * 12 + b2 * 6;
        m00 = M[0]; m01 = M[1]; m10 = M[2]; m11 = M[3]; c0 = M[4]; c1 = M[5];
        float qax = fmaf(m00, pax, fmaf(m01, pay, c0));   // v20(a)
        float qay = fmaf(m10, pax, fmaf(m11, pay, c1));
        float qbx = fmaf(m00, pbx, fmaf(m01, pby, c0));   // v20(b)
        float qby = fmaf(m10, pbx, fmaf(m11, pby, c1));

        unsigned p = t | (b1 << 18) | (b2 << 19);
        float4* o0 = reinterpret_cast<float4*>(out + (size_t)p * OUT_DIM);
        float4* o1 = reinterpret_cast<float4*>(out + ((size_t)p + (1u << 20)) * OUT_DIM);

        #pragma unroll
        for (int g = 0; g < 8; g++) {
            float4 r0, r1;
            #pragma unroll
            for (int e = 0; e < 4; e++) {
                int c = g * 4 + e;
                float2 w18 = W18[c], w19 = W19[c], w20 = W20[c];
                float P = fmaf(w18.x, vs18x, fmaf(w18.y, vs18y, A[c]));
                P = fmaf(w19.x, vs19x, fmaf(w19.y, vs19y, P));
                float v0 = fmaf(w20.x, qax, fmaf(w20.y, qay, P));
                float v1 = fmaf(w20.x, qbx, fmaf(w20.y, qby, P));
                (&r0.x)[e] = v0;
                (&r1.x)[e] = v1;
            }
            __stcs(o0 + g, r0);
            __stcs(o1 + g, r1);
        }
    }
}

// ---------------------------------------------------------------------------
extern "C" void kernel_launch(void* const* d_in, const int* in_sizes, int n_in,
                              void* d_out, int out_size)
{
    const float* x    = (const float*)d_in[0];
    const float* wl   = (const float*)d_in[1];
    const float* wr   = (const float*)d_in[2];
    const float* bl   = (const float*)d_in[3];
    const float* br   = (const float*)d_in[4];
    const float* tl   = (const float*)d_in[5];
    const float* tr   = (const float*)d_in[6];
    const float* tbl  = (const float*)d_in[7];
    const float* tbr  = (const float*)d_in[8];
    const float* w0   = (const float*)d_in[9];
    const float* wout = (const float*)d_in[10];
    const float* ob   = (const float*)d_in[11];

    precompute_kernel<<<N_PRE, 256>>>(x, wl, wr, bl, br, w0, ob);

    const int threads = 1 << PREFIX_BITS;
    tree_kernel<<<threads / 128, 128>>>(tl, tr, tbl, tbr, wout, (float*)d_out);
}

// round 3
// speedup vs baseline: 1.9346x; 1.9346x over previous
#include <cuda_runtime.h>

#define T_LEVELS    21
#define IN_DIM      4096
#define OUT_DIM     32
#define PREFIX_BITS 18         // bits s1..s18 = bits 0..17 of t
#define N_PRE       (4 + OUT_DIM)

// Scratch for precomputed dot products (allowed: __device__ global, no alloc).
__device__ float g_pre[N_PRE];

// ---------------------------------------------------------------------------
// Kernel 1: 36 dot products of x (4096) with rows of in_left/in_right/out_layer0
// ---------------------------------------------------------------------------
__global__ void precompute_kernel(const float* __restrict__ x,
                                  const float* __restrict__ wl,
                                  const float* __restrict__ wr,
                                  const float* __restrict__ bl,
                                  const float* __restrict__ br,
                                  const float* __restrict__ w0,
                                  const float* __restrict__ ob)
{
    int r = blockIdx.x;            // 0..35
    const float* src;
    if (r < 2)       src = wl + r * IN_DIM;
    else if (r < 4)  src = wr + (r - 2) * IN_DIM;
    else             src = w0 + (r - 4) * IN_DIM;

    const float4* x4 = reinterpret_cast<const float4*>(x);
    const float4* s4 = reinterpret_cast<const float4*>(src);
    float s = 0.0f;
    #pragma unroll
    for (int i = threadIdx.x; i < IN_DIM / 4; i += 256) {
        float4 a = x4[i], b = s4[i];
        s = fmaf(a.x, b.x, s);
        s = fmaf(a.y, b.y, s);
        s = fmaf(a.z, b.z, s);
        s = fmaf(a.w, b.w, s);
    }

    __shared__ float red[8];
    #pragma unroll
    for (int o = 16; o > 0; o >>= 1) s += __shfl_down_sync(0xffffffffu, s, o);
    if ((threadIdx.x & 31) == 0) red[threadIdx.x >> 5] = s;
    __syncthreads();
    if (threadIdx.x == 0) {
        float tot = 0.0f;
        for (int w = 0; w < 8; w++) tot += red[w];
        float add;
        if (r < 2)      add = bl[r];
        else if (r < 4) add = br[r - 2];
        else            add = ob[r - 4];
        g_pre[r] = tot + add;
    }
}

// ---------------------------------------------------------------------------
// Kernel 2: binary-tree expansion, channel-split.
// Thread = (path prefix t [18 bits], channel group c4 [3 bits]); it owns
// channels 4*c4..4*c4+3 of every row under prefix t. It enumerates suffix bits
// s19,s20 and leaf bit j0 -> 8 float4 stores.
// Warp lanes: c4 = lane&7, low 2 bits of t = lane>>3  =>  one STG.128 writes
// 512 CONTIGUOUS bytes (4 complete 128B rows). __stcs is safe: lines are fully
// covered by a single instruction, no L2 merge needed.
// ---------------------------------------------------------------------------
__global__ void __launch_bounds__(256)
tree_kernel(const float* __restrict__ tl,   // (21,2,2)
            const float* __restrict__ tr,   // (21,2,2)
            const float* __restrict__ tbl,  // (21,2)
            const float* __restrict__ tbr,  // (21,2)
            const float* __restrict__ wout, // (21,32,2)
            float* __restrict__ out)
{
    __shared__ float s_wout[T_LEVELS * 64];  // [k][c][j]
    __shared__ float s_tree[T_LEVELS * 12];  // [k][branch]{m00,m01,m10,m11,b0,b1}
    __shared__ float s_pre[N_PRE];

    for (int i = threadIdx.x; i < T_LEVELS * 64; i += blockDim.x)
        s_wout[i] = wout[i];
    for (int i = threadIdx.x; i < T_LEVELS * 12; i += blockDim.x) {
        int k = i / 12, rem = i % 12, b = rem / 6, e = rem % 6;
        const float* M = b ? tr  : tl;
        const float* B = b ? tbr : tbl;
        s_tree[i] = (e < 4) ? M[k * 4 + e] : B[k * 2 + (e - 4)];
    }
    for (int i = threadIdx.x; i < N_PRE; i += blockDim.x)
        s_pre[i] = g_pre[i];
    __syncthreads();

    const float2* s_wout2 = reinterpret_cast<const float2*>(s_wout);

    const unsigned gg = blockIdx.x * 256u + threadIdx.x;  // 2^21 threads
    const unsigned c4 = gg & 7u;                          // channel group
    const unsigned t  = gg >> 3;                          // 18-bit path prefix

    // A = this thread's 4 channels of the base accumulator
    float A0 = s_pre[4 + c4 * 4 + 0];
    float A1 = s_pre[4 + c4 * 4 + 1];
    float A2 = s_pre[4 + c4 * 4 + 2];
    float A3 = s_pre[4 + c4 * 4 + 3];
    float vax = s_pre[0], vay = s_pre[2];   // v0(0)
    float vbx = s_pre[1], vby = s_pre[3];   // v0(1)

    // ---- prefix walk: levels k = 0..17, branch bit = bit k of t ----
    #pragma unroll 1
    for (int k = 0; k < PREFIX_BITS; k++) {
        unsigned b = (t >> k) & 1u;
        const float2* W = s_wout2 + k * 32 + c4 * 4;
        float vsx = b ? vbx : vax;
        float vsy = b ? vby : vay;
        float2 w0 = W[0], w1 = W[1], w2 = W[2], w3 = W[3];
        A0 = fmaf(w0.x, vsx, fmaf(w0.y, vsy, A0));
        A1 = fmaf(w1.x, vsx, fmaf(w1.y, vsy, A1));
        A2 = fmaf(w2.x, vsx, fmaf(w2.y, vsy, A2));
        A3 = fmaf(w3.x, vsx, fmaf(w3.y, vsy, A3));
        const float* M = s_tree + k * 12 + b * 6;
        float m00 = M[0], m01 = M[1], m10 = M[2], m11 = M[3], c0 = M[4], c1 = M[5];
        float nax = fmaf(m00, vax, fmaf(m01, vay, c0));
        float nay = fmaf(m10, vax, fmaf(m11, vay, c1));
        float nbx = fmaf(m00, vbx, fmaf(m01, vby, c0));
        float nby = fmaf(m10, vbx, fmaf(m11, vby, c1));
        vax = nax; vay = nay; vbx = nbx; vby = nby;
    }

    const float2* W18 = s_wout2 + 18 * 32 + c4 * 4;
    const float2* W19 = s_wout2 + 19 * 32 + c4 * 4;
    const float2* W20 = s_wout2 + 20 * 32 + c4 * 4;
    float2 u18a = W18[0], u18b = W18[1], u18c = W18[2], u18d = W18[3];
    float2 u19a = W19[0], u19b = W19[1], u19c = W19[2], u19d = W19[3];
    float2 u20a = W20[0], u20b = W20[1], u20c = W20[2], u20d = W20[3];

    // ---- suffix enumeration: b1 = s19, b2 = s20; leaves j0 in {0,1} ----
    #pragma unroll
    for (unsigned u = 0; u < 4; ++u) {
        unsigned b1 = u & 1u, b2 = (u >> 1) & 1u;

        // level 18
        float vs18x = b1 ? vbx : vax;
        float vs18y = b1 ? vby : vay;
        const float* M = s_tree + 18 * 12 + b1 * 6;
        float m00 = M[0], m01 = M[1], m10 = M[2], m11 = M[3], c0 = M[4], c1 = M[5];
        float pax = fmaf(m00, vax, fmaf(m01, vay, c0));
        float pay = fmaf(m10, vax, fmaf(m11, vay, c1));
        float pbx = fmaf(m00, vbx, fmaf(m01, vby, c0));
        float pby = fmaf(m10, vbx, fmaf(m11, vby, c1));

        // level 19
        float vs19x = b2 ? pbx : pax;
        float vs19y = b2 ? pby : pay;
        M = s_tree + 19 * 12 + b2 * 6;
        m00 = M[0]; m01 = M[1]; m10 = M[2]; m11 = M[3]; c0 = M[4]; c1 = M[5];
        float qax = fmaf(m00, pax, fmaf(m01, pay, c0));
        float qay = fmaf(m10, pax, fmaf(m11, pay, c1));
        float qbx = fmaf(m00, pbx, fmaf(m01, pby, c0));
        float qby = fmaf(m10, pbx, fmaf(m11, pby, c1));

        // partial sums through level 19 for this thread's 4 channels
        float P0 = fmaf(u19a.x, vs19x, fmaf(u19a.y, vs19y,
                   fmaf(u18a.x, vs18x, fmaf(u18a.y, vs18y, A0))));
        float P1 = fmaf(u19b.x, vs19x, fmaf(u19b.y, vs19y,
                   fmaf(u18b.x, vs18x, fmaf(u18b.y, vs18y, A1))));
        float P2 = fmaf(u19c.x, vs19x, fmaf(u19c.y, vs19y,
                   fmaf(u18c.x, vs18x, fmaf(u18c.y, vs18y, A2))));
        float P3 = fmaf(u19d.x, vs19x, fmaf(u19d.y, vs19y,
                   fmaf(u18d.x, vs18x, fmaf(u18d.y, vs18y, A3))));

        unsigned p = t | (b1 << 18) | (b2 << 19);
        float* o = out + (size_t)p * OUT_DIM + c4 * 4;

        float4 r0, r1;
        r0.x = fmaf(u20a.x, qax, fmaf(u20a.y, qay, P0));
        r0.y = fmaf(u20b.x, qax, fmaf(u20b.y, qay, P1));
        r0.z = fmaf(u20c.x, qax, fmaf(u20c.y, qay, P2));
        r0.w = fmaf(u20d.x, qax, fmaf(u20d.y, qay, P3));
        r1.x = fmaf(u20a.x, qbx, fmaf(u20a.y, qby, P0));
        r1.y = fmaf(u20b.x, qbx, fmaf(u20b.y, qby, P1));
        r1.z = fmaf(u20c.x, qbx, fmaf(u20c.y, qby, P2));
        r1.w = fmaf(u20d.x, qbx, fmaf(u20d.y, qby, P3));

        __stcs(reinterpret_cast<float4*>(o), r0);
        __stcs(reinterpret_cast<float4*>(o + ((size_t)1u << 20) * OUT_DIM), r1);
    }
}

// ---------------------------------------------------------------------------
extern "C" void kernel_launch(void* const* d_in, const int* in_sizes, int n_in,
                              void* d_out, int out_size)
{
    const float* x    = (const float*)d_in[0];
    const float* wl   = (const float*)d_in[1];
    const float* wr   = (const float*)d_in[2];
    const float* bl   = (const float*)d_in[3];
    const float* br   = (const float*)d_in[4];
    const float* tl   = (const float*)d_in[5];
    const float* tr   = (const float*)d_in[6];
    const float* tbl  = (const float*)d_in[7];
    const float* tbr  = (const float*)d_in[8];
    const float* w0   = (const float*)d_in[9];
    const float* wout = (const float*)d_in[10];
    const float* ob   = (const float*)d_in[11];

    precompute_kernel<<<N_PRE, 256>>>(x, wl, wr, bl, br, w0, ob);

    const int total_threads = 1 << (PREFIX_BITS + 3);   // 2^21
    tree_kernel<<<total_threads / 256, 256>>>(tl, tr, tbl, tbr, wout, (float*)d_out);
}

// round 4
// speedup vs baseline: 2.8342x; 1.4650x over previous
#include <cuda_runtime.h>

#define T_LEVELS    21
#define IN_DIM      4096
#define OUT_DIM     32
#define BLK_BITS    13         // path bits s1..s13 handled once per block
#define PRIV_BITS   5          // path bits s14..s18, private per-thread walk
#define N_PRE       (4 + OUT_DIM)

// Scratch for precomputed dot products (allowed: __device__ global, no alloc).
__device__ float g_pre[N_PRE];

// ---------------------------------------------------------------------------
// Kernel 1: 36 dot products of x (4096) with rows of in_left/in_right/out_layer0
// ---------------------------------------------------------------------------
__global__ void precompute_kernel(const float* __restrict__ x,
                                  const float* __restrict__ wl,
                                  const float* __restrict__ wr,
                                  const float* __restrict__ bl,
                                  const float* __restrict__ br,
                                  const float* __restrict__ w0,
                                  const float* __restrict__ ob)
{
    int r = blockIdx.x;            // 0..35
    const float* src;
    if (r < 2)       src = wl + r * IN_DIM;
    else if (r < 4)  src = wr + (r - 2) * IN_DIM;
    else             src = w0 + (r - 4) * IN_DIM;

    const float4* x4 = reinterpret_cast<const float4*>(x);
    const float4* s4 = reinterpret_cast<const float4*>(src);
    float s = 0.0f;
    #pragma unroll
    for (int i = threadIdx.x; i < IN_DIM / 4; i += 256) {
        float4 a = x4[i], b = s4[i];
        s = fmaf(a.x, b.x, s);
        s = fmaf(a.y, b.y, s);
        s = fmaf(a.z, b.z, s);
        s = fmaf(a.w, b.w, s);
    }

    __shared__ float red[8];
    #pragma unroll
    for (int o = 16; o > 0; o >>= 1) s += __shfl_down_sync(0xffffffffu, s, o);
    if ((threadIdx.x & 31) == 0) red[threadIdx.x >> 5] = s;
    __syncthreads();
    if (threadIdx.x == 0) {
        float tot = 0.0f;
        for (int w = 0; w < 8; w++) tot += red[w];
        float add;
        if (r < 2)      add = bl[r];
        else if (r < 4) add = br[r - 2];
        else            add = ob[r - 4];
        g_pre[r] = tot + add;
    }
}

// ---------------------------------------------------------------------------
// Kernel 2: hierarchical binary-tree expansion.
//   Block  = 13-bit path prefix P (bits s1..s13). Stage 1: warp 0 computes the
//            13-level checkpoint (A13[32], v13) ONCE for the whole block.
//   Thread = (c4 = tid&7 channel group, r = tid>>3 = 5 private bits s14..s18).
//            Stage 2: walk levels 13..17 from the checkpoint, then enumerate
//            suffix bits s19,s20 and leaf j0 -> 8 float4 stores.
// Stores: 8 lanes with consecutive c4 cover one complete 128B row line.
// ---------------------------------------------------------------------------
__global__ void __launch_bounds__(256)
tree_kernel(const float* __restrict__ tl,   // (21,2,2)
            const float* __restrict__ tr,   // (21,2,2)
            const float* __restrict__ tbl,  // (21,2)
            const float* __restrict__ tbr,  // (21,2)
            const float* __restrict__ wout, // (21,32,2)
            float* __restrict__ out)
{
    __shared__ float s_wout[T_LEVELS * 64];  // [k][c][j]
    __shared__ float s_tree[T_LEVELS * 12];  // [k][branch]{m00,m01,m10,m11,b0,b1}
    __shared__ float s_pre[N_PRE];
    __shared__ float s_A13[OUT_DIM];         // block checkpoint accumulator
    __shared__ float s_v13[4];               // block checkpoint v (vax,vay,vbx,vby)

    for (int i = threadIdx.x; i < T_LEVELS * 64; i += blockDim.x)
        s_wout[i] = wout[i];
    for (int i = threadIdx.x; i < T_LEVELS * 12; i += blockDim.x) {
        int k = i / 12, rem = i % 12, b = rem / 6, e = rem % 6;
        const float* M = b ? tr  : tl;
        const float* B = b ? tbr : tbl;
        s_tree[i] = (e < 4) ? M[k * 4 + e] : B[k * 2 + (e - 4)];
    }
    for (int i = threadIdx.x; i < N_PRE; i += blockDim.x)
        s_pre[i] = g_pre[i];
    __syncthreads();

    const float2* s_wout2 = reinterpret_cast<const float2*>(s_wout);
    const unsigned P = blockIdx.x;            // 2^13 blocks: path bits s1..s13

    // ---- stage 1: warp 0 computes the 13-level checkpoint for this block ----
    if (threadIdx.x < 32) {
        int c = threadIdx.x;                  // one channel per thread
        float A = s_pre[4 + c];
        float vax = s_pre[0], vay = s_pre[2];
        float vbx = s_pre[1], vby = s_pre[3];
        #pragma unroll 1
        for (int k = 0; k < BLK_BITS; k++) {
            unsigned b = (P >> k) & 1u;
            float2 w = s_wout2[k * 32 + c];
            float vsx = b ? vbx : vax;
            float vsy = b ? vby : vay;
            A = fmaf(w.x, vsx, fmaf(w.y, vsy, A));
            const float* M = s_tree + k * 12 + b * 6;
            float m00 = M[0], m01 = M[1], m10 = M[2], m11 = M[3], c0 = M[4], c1 = M[5];
            float nax = fmaf(m00, vax, fmaf(m01, vay, c0));
            float nay = fmaf(m10, vax, fmaf(m11, vay, c1));
            float nbx = fmaf(m00, vbx, fmaf(m01, vby, c0));
            float nby = fmaf(m10, vbx, fmaf(m11, vby, c1));
            vax = nax; vay = nay; vbx = nbx; vby = nby;
        }
        s_A13[c] = A;
        if (c == 0) { s_v13[0] = vax; s_v13[1] = vay; s_v13[2] = vbx; s_v13[3] = vby; }
    }
    __syncthreads();

    // ---- stage 2: per-thread walk of private bits ----
    const unsigned c4 = threadIdx.x & 7u;     // channel group (4 channels)
    const unsigned r  = threadIdx.x >> 3;     // 5 bits: s14..s18

    float A0 = s_A13[c4 * 4 + 0];
    float A1 = s_A13[c4 * 4 + 1];
    float A2 = s_A13[c4 * 4 + 2];
    float A3 = s_A13[c4 * 4 + 3];
    float vax = s_v13[0], vay = s_v13[1];
    float vbx = s_v13[2], vby = s_v13[3];

    #pragma unroll
    for (int q = 0; q < PRIV_BITS; q++) {
        int k = BLK_BITS + q;                 // levels 13..17
        unsigned b = (r >> q) & 1u;
        const float2* W = s_wout2 + k * 32 + c4 * 4;
        float vsx = b ? vbx : vax;
        float vsy = b ? vby : vay;
        float2 w0 = W[0], w1 = W[1], w2 = W[2], w3 = W[3];
        A0 = fmaf(w0.x, vsx, fmaf(w0.y, vsy, A0));
        A1 = fmaf(w1.x, vsx, fmaf(w1.y, vsy, A1));
        A2 = fmaf(w2.x, vsx, fmaf(w2.y, vsy, A2));
        A3 = fmaf(w3.x, vsx, fmaf(w3.y, vsy, A3));
        const float* M = s_tree + k * 12 + b * 6;
        float m00 = M[0], m01 = M[1], m10 = M[2], m11 = M[3], c0 = M[4], c1 = M[5];
        float nax = fmaf(m00, vax, fmaf(m01, vay, c0));
        float nay = fmaf(m10, vax, fmaf(m11, vay, c1));
        float nbx = fmaf(m00, vbx, fmaf(m01, vby, c0));
        float nby = fmaf(m10, vbx, fmaf(m11, vby, c1));
        vax = nax; vay = nay; vbx = nbx; vby = nby;
    }

    // hoist suffix weights (levels 18,19,20) for this thread's 4 channels
    const float2* W18 = s_wout2 + 18 * 32 + c4 * 4;
    const float2* W19 = s_wout2 + 19 * 32 + c4 * 4;
    const float2* W20 = s_wout2 + 20 * 32 + c4 * 4;
    float2 u18a = W18[0], u18b = W18[1], u18c = W18[2], u18d = W18[3];
    float2 u19a = W19[0], u19b = W19[1], u19c = W19[2], u19d = W19[3];
    float2 u20a = W20[0], u20b = W20[1], u20c = W20[2], u20d = W20[3];

    const unsigned p_base = P | (r << BLK_BITS);   // 18 low path bits fixed

    // ---- suffix enumeration: b1 = s19 (level 18), b2 = s20 (level 19) ----
    #pragma unroll
    for (unsigned u = 0; u < 4; ++u) {
        unsigned b1 = u & 1u, b2 = (u >> 1) & 1u;

        // level 18
        float vs18x = b1 ? vbx : vax;
        float vs18y = b1 ? vby : vay;
        const float* M = s_tree + 18 * 12 + b1 * 6;
        float m00 = M[0], m01 = M[1], m10 = M[2], m11 = M[3], c0 = M[4], c1 = M[5];
        float pax = fmaf(m00, vax, fmaf(m01, vay, c0));
        float pay = fmaf(m10, vax, fmaf(m11, vay, c1));
        float pbx = fmaf(m00, vbx, fmaf(m01, vby, c0));
        float pby = fmaf(m10, vbx, fmaf(m11, vby, c1));

        // level 19
        float vs19x = b2 ? pbx : pax;
        float vs19y = b2 ? pby : pay;
        M = s_tree + 19 * 12 + b2 * 6;
        m00 = M[0]; m01 = M[1]; m10 = M[2]; m11 = M[3]; c0 = M[4]; c1 = M[5];
        float qax = fmaf(m00, pax, fmaf(m01, pay, c0));
        float qay = fmaf(m10, pax, fmaf(m11, pay, c1));
        float qbx = fmaf(m00, pbx, fmaf(m01, pby, c0));
        float qby = fmaf(m10, pbx, fmaf(m11, pby, c1));

        // partial sums through level 19 for this thread's 4 channels
        float P0 = fmaf(u19a.x, vs19x, fmaf(u19a.y, vs19y,
                   fmaf(u18a.x, vs18x, fmaf(u18a.y, vs18y, A0))));
        float P1 = fmaf(u19b.x, vs19x, fmaf(u19b.y, vs19y,
                   fmaf(u18b.x, vs18x, fmaf(u18b.y, vs18y, A1))));
        float P2 = fmaf(u19c.x, vs19x, fmaf(u19c.y, vs19y,
                   fmaf(u18c.x, vs18x, fmaf(u18c.y, vs18y, A2))));
        float P3 = fmaf(u19d.x, vs19x, fmaf(u19d.y, vs19y,
                   fmaf(u18d.x, vs18x, fmaf(u18d.y, vs18y, A3))));

        unsigned p = p_base | (b1 << 18) | (b2 << 19);
        float* o = out + (size_t)p * OUT_DIM + c4 * 4;

        float4 r0, r1;
        r0.x = fmaf(u20a.x, qax, fmaf(u20a.y, qay, P0));
        r0.y = fmaf(u20b.x, qax, fmaf(u20b.y, qay, P1));
        r0.z = fmaf(u20c.x, qax, fmaf(u20c.y, qay, P2));
        r0.w = fmaf(u20d.x, qax, fmaf(u20d.y, qay, P3));
        r1.x = fmaf(u20a.x, qbx, fmaf(u20a.y, qby, P0));
        r1.y = fmaf(u20b.x, qbx, fmaf(u20b.y, qby, P1));
        r1.z = fmaf(u20c.x, qbx, fmaf(u20c.y, qby, P2));
        r1.w = fmaf(u20d.x, qbx, fmaf(u20d.y, qby, P3));

        __stcs(reinterpret_cast<float4*>(o), r0);
        __stcs(reinterpret_cast<float4*>(o + ((size_t)1u << 20) * OUT_DIM), r1);
    }
}

// ---------------------------------------------------------------------------
extern "C" void kernel_launch(void* const* d_in, const int* in_sizes, int n_in,
                              void* d_out, int out_size)
{
    const float* x    = (const float*)d_in[0];
    const float* wl   = (const float*)d_in[1];
    const float* wr   = (const float*)d_in[2];
    const float* bl   = (const float*)d_in[3];
    const float* br   = (const float*)d_in[4];
    const float* tl   = (const float*)d_in[5];
    const float* tr   = (const float*)d_in[6];
    const float* tbl  = (const float*)d_in[7];
    const float* tbr  = (const float*)d_in[8];
    const float* w0   = (const float*)d_in[9];
    const float* wout = (const float*)d_in[10];
    const float* ob   = (const float*)d_in[11];

    precompute_kernel<<<N_PRE, 256>>>(x, wl, wr, bl, br, w0, ob);

    tree_kernel<<<(1 << BLK_BITS), 256>>>(tl, tr, tbl, tbr, wout, (float*)d_out);
}

// round 5
// speedup vs baseline: 3.2559x; 1.1488x over previous
#include <cuda_runtime.h>

#define T_LEVELS    21
#define IN_DIM      4096
#define OUT_DIM     32
#define BLK_BITS    13         // levels 0..12: once per block (warp 0)
#define N_PRE       (4 + OUT_DIM)

// Scratch for precomputed dot products (allowed: __device__ global, no alloc).
__device__ float g_pre[N_PRE];

// ---------------------------------------------------------------------------
// Kernel 1: 36 dot products of x (4096) with rows of in_left/in_right/out_layer0
// ---------------------------------------------------------------------------
__global__ void precompute_kernel(const float* __restrict__ x,
                                  const float* __restrict__ wl,
                                  const float* __restrict__ wr,
                                  const float* __restrict__ bl,
                                  const float* __restrict__ br,
                                  const float* __restrict__ w0,
                                  const float* __restrict__ ob)
{
    int r = blockIdx.x;            // 0..35
    const float* src;
    if (r < 2)       src = wl + r * IN_DIM;
    else if (r < 4)  src = wr + (r - 2) * IN_DIM;
    else             src = w0 + (r - 4) * IN_DIM;

    const float4* x4 = reinterpret_cast<const float4*>(x);
    const float4* s4 = reinterpret_cast<const float4*>(src);
    float s = 0.0f;
    #pragma unroll
    for (int i = threadIdx.x; i < IN_DIM / 4; i += 256) {
        float4 a = x4[i], b = s4[i];
        s = fmaf(a.x, b.x, s);
        s = fmaf(a.y, b.y, s);
        s = fmaf(a.z, b.z, s);
        s = fmaf(a.w, b.w, s);
    }

    __shared__ float red[8];
    #pragma unroll
    for (int o = 16; o > 0; o >>= 1) s += __shfl_down_sync(0xffffffffu, s, o);
    if ((threadIdx.x & 31) == 0) red[threadIdx.x >> 5] = s;
    __syncthreads();
    if (threadIdx.x == 0) {
        float tot = 0.0f;
        for (int w = 0; w < 8; w++) tot += red[w];
        float add;
        if (r < 2)      add = bl[r];
        else if (r < 4) add = br[r - 2];
        else            add = ob[r - 4];
        g_pre[r] = tot + add;
    }
}

// ---------------------------------------------------------------------------
// Kernel 2: 3-stage hierarchical binary-tree expansion.
//   Stage 1 (block):  warp 0 walks levels 0..12 (bits = blockIdx.x) once.
//   Stage 2 (warp):   each warp walks levels 13..15 (bits = warp id w),
//                     lane = channel, 1 LDS.64/level; A16 redistributed by SHFL.
//   Stage 3 (thread): lane bits rr (2) walk levels 16..17; suffix bits s19,s20
//                     and leaf j0 are enumerated with ALL constants hoisted to
//                     registers (u-loop is LDS-free).
// Row index: p = P | (w<<13) | (rr<<16) | (b1<<18) | (b2<<19), leaf bit 20.
// Store: 8 lanes (c4) cover one full 128B row; 4 rows per STG.128 instruction.
// ---------------------------------------------------------------------------
__global__ void __launch_bounds__(256)
tree_kernel(const float* __restrict__ tl,   // (21,2,2)
            const float* __restrict__ tr,   // (21,2,2)
            const float* __restrict__ tbl,  // (21,2)
            const float* __restrict__ tbr,  // (21,2)
            const float* __restrict__ wout, // (21,32,2)
            float* __restrict__ out)
{
    __shared__ float s_wout[T_LEVELS * 64];  // [k][c][j]
    __shared__ float s_tree[T_LEVELS * 12];  // [k][branch]{m00,m01,m10,m11,b0,b1}
    __shared__ float s_pre[N_PRE];
    __shared__ float s_A13[OUT_DIM];
    __shared__ float s_v13[4];

    for (int i = threadIdx.x; i < T_LEVELS * 64; i += blockDim.x)
        s_wout[i] = wout[i];
    for (int i = threadIdx.x; i < T_LEVELS * 12; i += blockDim.x) {
        int k = i / 12, rem = i % 12, b = rem / 6, e = rem % 6;
        const float* M = b ? tr  : tl;
        const float* B = b ? tbr : tbl;
        s_tree[i] = (e < 4) ? M[k * 4 + e] : B[k * 2 + (e - 4)];
    }
    for (int i = threadIdx.x; i < N_PRE; i += blockDim.x)
        s_pre[i] = g_pre[i];
    __syncthreads();

    const float2* s_wout2 = reinterpret_cast<const float2*>(s_wout);
    const unsigned P = blockIdx.x;                 // 13 bits: levels 0..12

    // ---- stage 1: warp 0 computes 13-level block checkpoint ----
    if (threadIdx.x < 32) {
        int c = threadIdx.x;
        float A = s_pre[4 + c];
        float vax = s_pre[0], vay = s_pre[2];
        float vbx = s_pre[1], vby = s_pre[3];
        #pragma unroll 1
        for (int k = 0; k < BLK_BITS; k++) {
            unsigned b = (P >> k) & 1u;
            float2 wv = s_wout2[k * 32 + c];
            float vsx = b ? vbx : vax;
            float vsy = b ? vby : vay;
            A = fmaf(wv.x, vsx, fmaf(wv.y, vsy, A));
            const float* M = s_tree + k * 12 + b * 6;
            float m00 = M[0], m01 = M[1], m10 = M[2], m11 = M[3], c0 = M[4], c1 = M[5];
            float nax = fmaf(m00, vax, fmaf(m01, vay, c0));
            float nay = fmaf(m10, vax, fmaf(m11, vay, c1));
            float nbx = fmaf(m00, vbx, fmaf(m01, vby, c0));
            float nby = fmaf(m10, vbx, fmaf(m11, vby, c1));
            vax = nax; vay = nay; vbx = nbx; vby = nby;
        }
        s_A13[c] = A;
        if (c == 0) { s_v13[0] = vax; s_v13[1] = vay; s_v13[2] = vbx; s_v13[3] = vby; }
    }
    __syncthreads();

    // ---- stage 2: warp-cooperative levels 13..15 (branch bits = warp id) ----
    const unsigned w    = threadIdx.x >> 5;        // 3 bits: levels 13..15
    const unsigned lane = threadIdx.x & 31u;

    float Ac  = s_A13[lane];                       // lane = channel
    float vax = s_v13[0], vay = s_v13[1];
    float vbx = s_v13[2], vby = s_v13[3];

    #pragma unroll
    for (int j = 0; j < 3; j++) {
        int k = BLK_BITS + j;                      // 13,14,15
        unsigned b = (w >> j) & 1u;
        float2 wv = s_wout2[k * 32 + lane];
        float vsx = b ? vbx : vax;
        float vsy = b ? vby : vay;
        Ac = fmaf(wv.x, vsx, fmaf(wv.y, vsy, Ac));
        const float* M = s_tree + k * 12 + b * 6;  // warp-uniform -> broadcast
        float m00 = M[0], m01 = M[1], m10 = M[2], m11 = M[3], c0 = M[4], c1 = M[5];
        float nax = fmaf(m00, vax, fmaf(m01, vay, c0));
        float nay = fmaf(m10, vax, fmaf(m11, vay, c1));
        float nbx = fmaf(m00, vbx, fmaf(m01, vby, c0));
        float nby = fmaf(m10, vbx, fmaf(m11, vby, c1));
        vax = nax; vay = nay; vbx = nbx; vby = nby;
    }

    // redistribute A16: thread (c4, rr) takes channels 4*c4..4*c4+3
    const unsigned c4 = lane & 7u;
    const unsigned rr = lane >> 3;                 // 2 bits: levels 16..17
    float A0 = __shfl_sync(0xffffffffu, Ac, c4 * 4 + 0);
    float A1 = __shfl_sync(0xffffffffu, Ac, c4 * 4 + 1);
    float A2 = __shfl_sync(0xffffffffu, Ac, c4 * 4 + 2);
    float A3 = __shfl_sync(0xffffffffu, Ac, c4 * 4 + 3);

    // ---- stage 3a: private levels 16,17 (branch bits = rr) ----
    #pragma unroll
    for (int j = 0; j < 2; j++) {
        int k = 16 + j;
        unsigned b = (rr >> j) & 1u;
        const float2* W = s_wout2 + k * 32 + c4 * 4;
        float vsx = b ? vbx : vax;
        float vsy = b ? vby : vay;
        float2 w0 = W[0], w1 = W[1], w2 = W[2], w3 = W[3];
        A0 = fmaf(w0.x, vsx, fmaf(w0.y, vsy, A0));
        A1 = fmaf(w1.x, vsx, fmaf(w1.y, vsy, A1));
        A2 = fmaf(w2.x, vsx, fmaf(w2.y, vsy, A2));
        A3 = fmaf(w3.x, vsx, fmaf(w3.y, vsy, A3));
        const float* M = s_tree + k * 12 + b * 6;
        float m00 = M[0], m01 = M[1], m10 = M[2], m11 = M[3], c0 = M[4], c1 = M[5];
        float nax = fmaf(m00, vax, fmaf(m01, vay, c0));
        float nay = fmaf(m10, vax, fmaf(m11, vay, c1));
        float nbx = fmaf(m00, vbx, fmaf(m01, vby, c0));
        float nby = fmaf(m10, vbx, fmaf(m11, vby, c1));
        vax = nax; vay = nay; vbx = nbx; vby = nby;
    }

    // ---- hoist ALL suffix constants into registers (u-loop is LDS-free) ----
    const float2* W18 = s_wout2 + 18 * 32 + c4 * 4;
    const float2* W19 = s_wout2 + 19 * 32 + c4 * 4;
    const float2* W20 = s_wout2 + 20 * 32 + c4 * 4;
    float2 u18a = W18[0], u18b = W18[1], u18c = W18[2], u18d = W18[3];
    float2 u19a = W19[0], u19b = W19[1], u19c = W19[2], u19d = W19[3];
    float2 u20a = W20[0], u20b = W20[1], u20c = W20[2], u20d = W20[3];
    float M18[12], M19[12];
    #pragma unroll
    for (int i = 0; i < 12; i++) M18[i] = s_tree[18 * 12 + i];
    #pragma unroll
    for (int i = 0; i < 12; i++) M19[i] = s_tree[19 * 12 + i];

    const unsigned p_base = P | (w << 13) | (rr << 16);

    // ---- suffix enumeration: b1 = s19 (level 18), b2 = s20 (level 19) ----
    #pragma unroll
    for (unsigned u = 0; u < 4; ++u) {
        const unsigned b1 = u & 1u, b2 = (u >> 1) & 1u;

        // level 18 (constants from regs)
        float vs18x = b1 ? vbx : vax;
        float vs18y = b1 ? vby : vay;
        float m00 = M18[b1 * 6 + 0], m01 = M18[b1 * 6 + 1];
        float m10 = M18[b1 * 6 + 2], m11 = M18[b1 * 6 + 3];
        float c0  = M18[b1 * 6 + 4], c1  = M18[b1 * 6 + 5];
        float pax = fmaf(m00, vax, fmaf(m01, vay, c0));
        float pay = fmaf(m10, vax, fmaf(m11, vay, c1));
        float pbx = fmaf(m00, vbx, fmaf(m01, vby, c0));
        float pby = fmaf(m10, vbx, fmaf(m11, vby, c1));

        // level 19
        float vs19x = b2 ? pbx : pax;
        float vs19y = b2 ? pby : pay;
        m00 = M19[b2 * 6 + 0]; m01 = M19[b2 * 6 + 1];
        m10 = M19[b2 * 6 + 2]; m11 = M19[b2 * 6 + 3];
        c0  = M19[b2 * 6 + 4]; c1  = M19[b2 * 6 + 5];
        float qax = fmaf(m00, pax, fmaf(m01, pay, c0));
        float qay = fmaf(m10, pax, fmaf(m11, pay, c1));
        float qbx = fmaf(m00, pbx, fmaf(m01, pby, c0));
        float qby = fmaf(m10, pbx, fmaf(m11, pby, c1));

        float P0 = fmaf(u19a.x, vs19x, fmaf(u19a.y, vs19y,
                   fmaf(u18a.x, vs18x, fmaf(u18a.y, vs18y, A0))));
        float P1 = fmaf(u19b.x, vs19x, fmaf(u19b.y, vs19y,
                   fmaf(u18b.x, vs18x, fmaf(u18b.y, vs18y, A1))));
        float P2 = fmaf(u19c.x, vs19x, fmaf(u19c.y, vs19y,
                   fmaf(u18c.x, vs18x, fmaf(u18c.y, vs18y, A2))));
        float P3 = fmaf(u19d.x, vs19x, fmaf(u19d.y, vs19y,
                   fmaf(u18d.x, vs18x, fmaf(u18d.y, vs18y, A3))));

        unsigned p = p_base | (b1 << 18) | (b2 << 19);
        float* o = out + (size_t)p * OUT_DIM + c4 * 4;

        float4 r0, r1;
        r0.x = fmaf(u20a.x, qax, fmaf(u20a.y, qay, P0));
        r0.y = fmaf(u20b.x, qax, fmaf(u20b.y, qay, P1));
        r0.z = fmaf(u20c.x, qax, fmaf(u20c.y, qay, P2));
        r0.w = fmaf(u20d.x, qax, fmaf(u20d.y, qay, P3));
        r1.x = fmaf(u20a.x, qbx, fmaf(u20a.y, qby, P0));
        r1.y = fmaf(u20b.x, qbx, fmaf(u20b.y, qby, P1));
        r1.z = fmaf(u20c.x, qbx, fmaf(u20c.y, qby, P2));
        r1.w = fmaf(u20d.x, qbx, fmaf(u20d.y, qby, P3));

        __stcs(reinterpret_cast<float4*>(o), r0);
        __stcs(reinterpret_cast<float4*>(o + ((size_t)1u << 20) * OUT_DIM), r1);
    }
}

// ---------------------------------------------------------------------------
extern "C" void kernel_launch(void* const* d_in, const int* in_sizes, int n_in,
                              void* d_out, int out_size)
{
    const float* x    = (const float*)d_in[0];
    const float* wl   = (const float*)d_in[1];
    const float* wr   = (const float*)d_in[2];
    const float* bl   = (const float*)d_in[3];
    const float* br   = (const float*)d_in[4];
    const float* tl   = (const float*)d_in[5];
    const float* tr   = (const float*)d_in[6];
    const float* tbl  = (const float*)d_in[7];
    const float* tbr  = (const float*)d_in[8];
    const float* w0   = (const float*)d_in[9];
    const float* wout = (const float*)d_in[10];
    const float* ob   = (const float*)d_in[11];

    precompute_kernel<<<N_PRE, 256>>>(x, wl, wr, bl, br, w0, ob);

    tree_kernel<<<(1 << BLK_BITS), 256>>>(tl, tr, tbl, tbr, wout, (float*)d_out);
}

// round 6
// speedup vs baseline: 4.5171x; 1.3874x over previous
#include <cuda_runtime.h>

#define T_LEVELS    21
#define IN_DIM      4096
#define OUT_DIM     32
#define BLK_BITS    13         // levels 0..12, bits of prefix P
#define PPB         8          // prefixes per block (= warps per block)
#define N_PRE       (4 + OUT_DIM)

// Scratch for precomputed dot products (allowed: __device__ global, no alloc).
__device__ float g_pre[N_PRE];

// ---------------------------------------------------------------------------
// Kernel 1: 36 dot products of x (4096) with rows of in_left/in_right/out_layer0
// ---------------------------------------------------------------------------
__global__ void precompute_kernel(const float* __restrict__ x,
                                  const float* __restrict__ wl,
                                  const float* __restrict__ wr,
                                  const float* __restrict__ bl,
                                  const float* __restrict__ br,
                                  const float* __restrict__ w0,
                                  const float* __restrict__ ob)
{
    int r = blockIdx.x;            // 0..35
    const float* src;
    if (r < 2)       src = wl + r * IN_DIM;
    else if (r < 4)  src = wr + (r - 2) * IN_DIM;
    else             src = w0 + (r - 4) * IN_DIM;

    const float4* x4 = reinterpret_cast<const float4*>(x);
    const float4* s4 = reinterpret_cast<const float4*>(src);
    float s = 0.0f;
    #pragma unroll
    for (int i = threadIdx.x; i < IN_DIM / 4; i += 256) {
        float4 a = x4[i], b = s4[i];
        s = fmaf(a.x, b.x, s);
        s = fmaf(a.y, b.y, s);
        s = fmaf(a.z, b.z, s);
        s = fmaf(a.w, b.w, s);
    }

    __shared__ float red[8];
    #pragma unroll
    for (int o = 16; o > 0; o >>= 1) s += __shfl_down_sync(0xffffffffu, s, o);
    if ((threadIdx.x & 31) == 0) red[threadIdx.x >> 5] = s;
    __syncthreads();
    if (threadIdx.x == 0) {
        float tot = 0.0f;
        for (int w = 0; w < 8; w++) tot += red[w];
        float add;
        if (r < 2)      add = bl[r];
        else if (r < 4) add = br[r - 2];
        else            add = ob[r - 4];
        g_pre[r] = tot + add;
    }
}

// ---------------------------------------------------------------------------
// Kernel 2: hierarchical binary-tree expansion, 8 prefixes per block.
//   Phase 1 (parallel): warp w computes the 13-level checkpoint for prefix
//                       P = blockIdx*8 + w into s_A13[w]/s_v13[w]. One sync.
//   Phase 2 (loop over it=0..7): all warps expand checkpoint[it]:
//       stage 2: levels 13..15, branch bits = warp id (lane = channel),
//                A16 redistributed via SHFL;
//       stage 3: levels 16..17, branch bits = rr (lane>>3);
//       suffix:  levels 18..20 fully register-hoisted (LDS-free), 8 STG.128.
// Row index: p = P | (w<<13) | (rr<<16) | (b1<<18) | (b2<<19), leaf = bit 20.
// Store: 8 lanes (c4 = lane&7) cover one full 128B row line.
// ---------------------------------------------------------------------------
__global__ void __launch_bounds__(256, 4)
tree_kernel(const float* __restrict__ tl,   // (21,2,2)
            const float* __restrict__ tr,   // (21,2,2)
            const float* __restrict__ tbl,  // (21,2)
            const float* __restrict__ tbr,  // (21,2)
            const float* __restrict__ wout, // (21,32,2)
            float* __restrict__ out)
{
    __shared__ float s_wout[T_LEVELS * 64];  // [k][c][j]
    __shared__ float s_tree[T_LEVELS * 12];  // [k][branch]{m00,m01,m10,m11,b0,b1}
    __shared__ float s_pre[N_PRE];
    __shared__ float s_A13[PPB][OUT_DIM];
    __shared__ float s_v13[PPB][4];

    for (int i = threadIdx.x; i < T_LEVELS * 64; i += blockDim.x)
        s_wout[i] = wout[i];
    for (int i = threadIdx.x; i < T_LEVELS * 12; i += blockDim.x) {
        int k = i / 12, rem = i % 12, b = rem / 6, e = rem % 6;
        const float* M = b ? tr  : tl;
        const float* B = b ? tbr : tbl;
        s_tree[i] = (e < 4) ? M[k * 4 + e] : B[k * 2 + (e - 4)];
    }
    for (int i = threadIdx.x; i < N_PRE; i += blockDim.x)
        s_pre[i] = g_pre[i];
    __syncthreads();

    const float2* s_wout2 = reinterpret_cast<const float2*>(s_wout);
    const unsigned w    = threadIdx.x >> 5;        // warp id: stage-1 owner AND level 13..15 bits
    const unsigned lane = threadIdx.x & 31u;
    const unsigned Pb   = blockIdx.x * PPB;

    // ---- phase 1 (parallel): warp w computes checkpoint for prefix Pb + w ----
    {
        const unsigned P = Pb + w;
        int c = lane;                               // lane = channel
        float A = s_pre[4 + c];
        float vax = s_pre[0], vay = s_pre[2];
        float vbx = s_pre[1], vby = s_pre[3];
        #pragma unroll 1
        for (int k = 0; k < BLK_BITS; k++) {
            unsigned b = (P >> k) & 1u;
            float2 wv = s_wout2[k * 32 + c];
            float vsx = b ? vbx : vax;
            float vsy = b ? vby : vay;
            A = fmaf(wv.x, vsx, fmaf(wv.y, vsy, A));
            const float* M = s_tree + k * 12 + b * 6;
            float m00 = M[0], m01 = M[1], m10 = M[2], m11 = M[3], c0 = M[4], c1 = M[5];
            float nax = fmaf(m00, vax, fmaf(m01, vay, c0));
            float nay = fmaf(m10, vax, fmaf(m11, vay, c1));
            float nbx = fmaf(m00, vbx, fmaf(m01, vby, c0));
            float nby = fmaf(m10, vbx, fmaf(m11, vby, c1));
            vax = nax; vay = nay; vbx = nbx; vby = nby;
        }
        s_A13[w][c] = A;
        if (lane == 0) {
            s_v13[w][0] = vax; s_v13[w][1] = vay;
            s_v13[w][2] = vbx; s_v13[w][3] = vby;
        }
    }
    __syncthreads();

    const unsigned c4 = lane & 7u;                 // channel group
    const unsigned rr = lane >> 3;                 // 2 bits: levels 16..17

    // ---- hoist all suffix constants once (loop body is LDS-free at 18..20) ----
    const float2* W18 = s_wout2 + 18 * 32 + c4 * 4;
    const float2* W19 = s_wout2 + 19 * 32 + c4 * 4;
    const float2* W20 = s_wout2 + 20 * 32 + c4 * 4;
    float2 u18a = W18[0], u18b = W18[1], u18c = W18[2], u18d = W18[3];
    float2 u19a = W19[0], u19b = W19[1], u19c = W19[2], u19d = W19[3];
    float2 u20a = W20[0], u20b = W20[1], u20c = W20[2], u20d = W20[3];
    float M18[12], M19[12];
    #pragma unroll
    for (int i = 0; i < 12; i++) M18[i] = s_tree[18 * 12 + i];
    #pragma unroll
    for (int i = 0; i < 12; i++) M19[i] = s_tree[19 * 12 + i];

    // ---- phase 2: expand each of the 8 checkpoints ----
    #pragma unroll 1
    for (int it = 0; it < PPB; ++it) {
        float Ac  = s_A13[it][lane];
        float vax = s_v13[it][0], vay = s_v13[it][1];
        float vbx = s_v13[it][2], vby = s_v13[it][3];

        // stage 2: levels 13..15, branch bits = w (warp-uniform tree loads)
        #pragma unroll
        for (int j = 0; j < 3; j++) {
            int k = BLK_BITS + j;
            unsigned b = (w >> j) & 1u;
            float2 wv = s_wout2[k * 32 + lane];
            float vsx = b ? vbx : vax;
            float vsy = b ? vby : vay;
            Ac = fmaf(wv.x, vsx, fmaf(wv.y, vsy, Ac));
            const float* M = s_tree + k * 12 + b * 6;
            float m00 = M[0], m01 = M[1], m10 = M[2], m11 = M[3], c0 = M[4], c1 = M[5];
            float nax = fmaf(m00, vax, fmaf(m01, vay, c0));
            float nay = fmaf(m10, vax, fmaf(m11, vay, c1));
            float nbx = fmaf(m00, vbx, fmaf(m01, vby, c0));
            float nby = fmaf(m10, vbx, fmaf(m11, vby, c1));
            vax = nax; vay = nay; vbx = nbx; vby = nby;
        }

        // redistribute A16: thread (c4, rr) takes channels 4*c4..4*c4+3
        float A0 = __shfl_sync(0xffffffffu, Ac, c4 * 4 + 0);
        float A1 = __shfl_sync(0xffffffffu, Ac, c4 * 4 + 1);
        float A2 = __shfl_sync(0xffffffffu, Ac, c4 * 4 + 2);
        float A3 = __shfl_sync(0xffffffffu, Ac, c4 * 4 + 3);

        // stage 3a: levels 16,17 (branch bits = rr)
        #pragma unroll
        for (int j = 0; j < 2; j++) {
            int k = 16 + j;
            unsigned b = (rr >> j) & 1u;
            const float2* W = s_wout2 + k * 32 + c4 * 4;
            float vsx = b ? vbx : vax;
            float vsy = b ? vby : vay;
            float2 w0 = W[0], w1 = W[1], w2 = W[2], w3 = W[3];
            A0 = fmaf(w0.x, vsx, fmaf(w0.y, vsy, A0));
            A1 = fmaf(w1.x, vsx, fmaf(w1.y, vsy, A1));
            A2 = fmaf(w2.x, vsx, fmaf(w2.y, vsy, A2));
            A3 = fmaf(w3.x, vsx, fmaf(w3.y, vsy, A3));
            const float* M = s_tree + k * 12 + b * 6;
            float m00 = M[0], m01 = M[1], m10 = M[2], m11 = M[3], c0 = M[4], c1 = M[5];
            float nax = fmaf(m00, vax, fmaf(m01, vay, c0));
            float nay = fmaf(m10, vax, fmaf(m11, vay, c1));
            float nbx = fmaf(m00, vbx, fmaf(m01, vby, c0));
            float nby = fmaf(m10, vbx, fmaf(m11, vby, c1));
            vax = nax; vay = nay; vbx = nbx; vby = nby;
        }

        const unsigned p_base = (Pb + it) | (w << 13) | (rr << 16);

        // suffix enumeration: b1 = s19 (level 18), b2 = s20 (level 19)
        #pragma unroll
        for (unsigned u = 0; u < 4; ++u) {
            const unsigned b1 = u & 1u, b2 = (u >> 1) & 1u;

            float vs18x = b1 ? vbx : vax;
            float vs18y = b1 ? vby : vay;
            float m00 = M18[b1 * 6 + 0], m01 = M18[b1 * 6 + 1];
            float m10 = M18[b1 * 6 + 2], m11 = M18[b1 * 6 + 3];
            float c0  = M18[b1 * 6 + 4], c1  = M18[b1 * 6 + 5];
            float pax = fmaf(m00, vax, fmaf(m01, vay, c0));
            float pay = fmaf(m10, vax, fmaf(m11, vay, c1));
            float pbx = fmaf(m00, vbx, fmaf(m01, vby, c0));
            float pby = fmaf(m10, vbx, fmaf(m11, vby, c1));

            float vs19x = b2 ? pbx : pax;
            float vs19y = b2 ? pby : pay;
            m00 = M19[b2 * 6 + 0]; m01 = M19[b2 * 6 + 1];
            m10 = M19[b2 * 6 + 2]; m11 = M19[b2 * 6 + 3];
            c0  = M19[b2 * 6 + 4]; c1  = M19[b2 * 6 + 5];
            float qax = fmaf(m00, pax, fmaf(m01, pay, c0));
            float qay = fmaf(m10, pax, fmaf(m11, pay, c1));
            float qbx = fmaf(m00, pbx, fmaf(m01, pby, c0));
            float qby = fmaf(m10, pbx, fmaf(m11, pby, c1));

            float P0 = fmaf(u19a.x, vs19x, fmaf(u19a.y, vs19y,
                       fmaf(u18a.x, vs18x, fmaf(u18a.y, vs18y, A0))));
            float P1 = fmaf(u19b.x, vs19x, fmaf(u19b.y, vs19y,
                       fmaf(u18b.x, vs18x, fmaf(u18b.y, vs18y, A1))));
            float P2 = fmaf(u19c.x, vs19x, fmaf(u19c.y, vs19y,
                       fmaf(u18c.x, vs18x, fmaf(u18c.y, vs18y, A2))));
            float P3 = fmaf(u19d.x, vs19x, fmaf(u19d.y, vs19y,
                       fmaf(u18d.x, vs18x, fmaf(u18d.y, vs18y, A3))));

            unsigned p = p_base | (b1 << 18) | (b2 << 19);
            float* o = out + (size_t)p * OUT_DIM + c4 * 4;

            float4 r0, r1;
            r0.x = fmaf(u20a.x, qax, fmaf(u20a.y, qay, P0));
            r0.y = fmaf(u20b.x, qax, fmaf(u20b.y, qay, P1));
            r0.z = fmaf(u20c.x, qax, fmaf(u20c.y, qay, P2));
            r0.w = fmaf(u20d.x, qax, fmaf(u20d.y, qay, P3));
            r1.x = fmaf(u20a.x, qbx, fmaf(u20a.y, qby, P0));
            r1.y = fmaf(u20b.x, qbx, fmaf(u20b.y, qby, P1));
            r1.z = fmaf(u20c.x, qbx, fmaf(u20c.y, qby, P2));
            r1.w = fmaf(u20d.x, qbx, fmaf(u20d.y, qby, P3));

            __stcs(reinterpret_cast<float4*>(o), r0);
            __stcs(reinterpret_cast<float4*>(o + ((size_t)1u << 20) * OUT_DIM), r1);
        }
    }
}

// ---------------------------------------------------------------------------
extern "C" void kernel_launch(void* const* d_in, const int* in_sizes, int n_in,
                              void* d_out, int out_size)
{
    const float* x    = (const float*)d_in[0];
    const float* wl   = (const float*)d_in[1];
    const float* wr   = (const float*)d_in[2];
    const float* bl   = (const float*)d_in[3];
    const float* br   = (const float*)d_in[4];
    const float* tl   = (const float*)d_in[5];
    const float* tr   = (const float*)d_in[6];
    const float* tbl  = (const float*)d_in[7];
    const float* tbr  = (const float*)d_in[8];
    const float* w0   = (const float*)d_in[9];
    const float* wout = (const float*)d_in[10];
    const float* ob   = (const float*)d_in[11];

    precompute_kernel<<<N_PRE, 256>>>(x, wl, wr, bl, br, w0, ob);

    tree_kernel<<<(1 << BLK_BITS) / PPB, 256>>>(tl, tr, tbl, tbr, wout, (float*)d_out);
}